// round 15
// baseline (speedup 1.0000x reference)
#include <cuda_runtime.h>
#include <cuda_fp16.h>
#include <cstdint>
#include <math.h>

// Problem constants
#define BB 8
#define NN 2048
#define DD 256
#define SS 128
#define HH 512
#define EE 1152          // 2H + S
#define BNROWS (BB*NN)   // 16384
#define RSQRT_S 0.08838834764831845f  // 1/sqrt(128)

// ---- scratch (allocation-free rule: __device__ globals) ----
__device__ __half d_x16[(size_t)BNROWS*DD];          // xn fp16 (truncated)
__device__ __half d_u16[(size_t)BNROWS*HH];          // u fp16
__device__ __half d_q16[(size_t)BNROWS*SS];          // q fp16
__device__ __half d_k16[(size_t)BNROWS*SS];          // k fp16
__device__ __half d_vT[(size_t)BB*HH*NN];            // [b][h][m] fp16
__device__ __half d_ghi[(size_t)BNROWS*HH];          // gated fp16
__device__ __half d_wuvT16[(size_t)EE*DD];           // W_uv^T [e][d] fp16
__device__ __half d_woT[(size_t)DD*HH];              // W_o^T [d][h] fp16

// ============================================================
// Helpers
// ============================================================
__device__ __forceinline__ uint32_t smem_u32(const void* p) {
    uint32_t a;
    asm("{ .reg .u64 t; cvta.to.shared.u64 t, %1; cvt.u32.u64 %0, t; }"
        : "=r"(a) : "l"(p));
    return a;
}

#define LDSM_X4(r0, r1, r2, r3, addr) \
    asm volatile("ldmatrix.sync.aligned.m8n8.x4.shared.b16 {%0,%1,%2,%3}, [%4];" \
        : "=r"(r0), "=r"(r1), "=r"(r2), "=r"(r3) : "r"(addr))

#define MMA_F16(d, a, b) \
    asm volatile("mma.sync.aligned.m16n8k16.row.col.f32.f16.f16.f32 " \
        "{%0,%1,%2,%3}, {%4,%5,%6,%7}, {%8,%9}, {%0,%1,%2,%3};" \
        : "+f"((d)[0]), "+f"((d)[1]), "+f"((d)[2]), "+f"((d)[3]) \
        : "r"((a)[0]), "r"((a)[1]), "r"((a)[2]), "r"((a)[3]), \
          "r"((b)[0]), "r"((b)[1]))

__device__ __forceinline__ void cp16(uint32_t dst, const void* src) {
    asm volatile("cp.async.cg.shared.global [%0], [%1], 16;"
        :: "r"(dst), "l"(src));
}
#define CP_COMMIT() asm volatile("cp.async.commit_group;" ::: "memory")
#define CP_WAIT1()  asm volatile("cp.async.wait_group 1;" ::: "memory")

__device__ __forceinline__ uint32_t packh2(float x, float y) {
    __half2 h = __floats2half2_rn(x, y);
    return *reinterpret_cast<uint32_t*>(&h);
}

// 16B granule loader: ROWS*8 granules strided by 256 threads, 128B rows,
// swizzle gi ^= row&7.
template <int ROWS, class T>
__device__ __forceinline__ void load_oper(uint32_t dstBase, const T* src,
                                          int ld, int kt, int tid) {
    #pragma unroll
    for (int j = 0; j < ROWS*8/256; j++) {
        int g = tid + j * 256;
        int row = g >> 3;
        int gi  = g & 7;
        int gis = gi ^ (row & 7);
        cp16(dstBase + row * 128 + gis * 16, src + (size_t)row * ld + kt + gi * 8);
    }
}

// ============================================================
// fp16 single-term GEMM core: BM=128, BN=128, BK=64, 3-stage, 2 CTAs/SM.
// ============================================================
#define STAGE_S  32768
#define SMEM_S1  (3*STAGE_S)

__device__ __forceinline__ void load_chunk_s(uint32_t sb, int stage,
        const __half* Ah, int ldA, const __half* Bh, int ldB, int kt, int tid) {
    uint32_t st = sb + stage * STAGE_S;
    load_oper<128>(st,         Ah, ldA, kt, tid);
    load_oper<128>(st + 16384, Bh, ldB, kt, tid);
}

__device__ __forceinline__ void compute_chunk_s(uint32_t st, int lane, int wm, int wn,
                                                float acc[2][8][4]) {
    const uint32_t aH = st, bH = st + 16384;
    #pragma unroll
    for (int ks = 0; ks < 4; ks++) {
        uint32_t Ahf[2][4];
        #pragma unroll
        for (int mi = 0; mi < 2; mi++) {
            int row = wm * 32 + mi * 16 + (lane & 15);
            int gi  = ks * 2 + (lane >> 4);
            uint32_t off = row * 128 + ((gi ^ (row & 7)) * 16);
            LDSM_X4(Ahf[mi][0], Ahf[mi][1], Ahf[mi][2], Ahf[mi][3], aH + off);
        }
        uint32_t Bhf[8][2];
        #pragma unroll
        for (int np = 0; np < 4; np++) {
            int row = wn * 64 + np * 16 + (lane & 7) + ((lane >> 4) << 3);
            int gi  = ks * 2 + ((lane >> 3) & 1);
            uint32_t off = row * 128 + ((gi ^ (row & 7)) * 16);
            LDSM_X4(Bhf[2*np][0], Bhf[2*np][1], Bhf[2*np+1][0], Bhf[2*np+1][1], bH + off);
        }
        #pragma unroll
        for (int mi = 0; mi < 2; mi++)
            #pragma unroll
            for (int ni = 0; ni < 8; ni++)
                MMA_F16(acc[mi][ni], Ahf[mi], Bhf[ni]);
    }
}

template <bool SYNC_BEFORE_EPI, class Epi>
__device__ __forceinline__ void core_f16s(
        const __half* Ah, int ldA, const __half* Bh, int ldB,
        int K, char* smem, Epi epi) {
    uint32_t sb = smem_u32(smem);
    int tid = threadIdx.x;
    int lane = tid & 31, warp = tid >> 5;
    int wm = warp & 3, wn = warp >> 2;

    float acc[2][8][4] = {};
    const int nc = K / 64;

    load_chunk_s(sb, 0, Ah, ldA, Bh, ldB, 0, tid);
    CP_COMMIT();
    if (nc > 1) load_chunk_s(sb, 1, Ah, ldA, Bh, ldB, 64, tid);
    CP_COMMIT();

    for (int c = 0; c < nc; c++) {
        CP_WAIT1();
        __syncthreads();
        if (c + 2 < nc) {
            int s = (c + 2) % 3;
            load_chunk_s(sb, s, Ah, ldA, Bh, ldB, (c + 2) * 64, tid);
        }
        CP_COMMIT();
        compute_chunk_s(sb + (c % 3) * STAGE_S, lane, wm, wn, acc);
    }

    if (SYNC_BEFORE_EPI) __syncthreads();

    #pragma unroll
    for (int mi = 0; mi < 2; mi++)
        #pragma unroll
        for (int ni = 0; ni < 8; ni++) {
            int r = wm * 32 + mi * 16 + (lane >> 2);
            int c = wn * 64 + ni * 8 + (lane & 3) * 2;
            epi(r,     c, acc[mi][ni][0], acc[mi][ni][1]);
            epi(r + 8, c, acc[mi][ni][2], acc[mi][ni][3]);
        }
}

// ============================================================
// prep + transposes
// ============================================================
__global__ void prep_x_kernel(const float* __restrict__ x,
                              const float* __restrict__ g) {
    int row  = blockIdx.x * blockDim.y + threadIdx.y;
    int lane = threadIdx.x;
    const float4* xr = reinterpret_cast<const float4*>(x + (size_t)row * DD);
    float4 a = xr[lane];
    float4 b = xr[lane + 32];
    float s = a.x*a.x + a.y*a.y + a.z*a.z + a.w*a.w
            + b.x*b.x + b.y*b.y + b.z*b.z + b.w*b.w;
    #pragma unroll
    for (int off = 16; off; off >>= 1) s += __shfl_xor_sync(0xffffffffu, s, off);
    s = __shfl_sync(0xffffffffu, s, 0);
    float norm = sqrtf(s * (1.0f / DD));
    float scale = g[0] / fmaxf(norm, 1e-5f);

    float va[8] = {a.x, a.y, a.z, a.w, b.x, b.y, b.z, b.w};
    int idx[2] = {lane * 4, 128 + lane * 4};
    #pragma unroll
    for (int h = 0; h < 2; h++)
        #pragma unroll
        for (int j = 0; j < 4; j++) {
            float v = va[h*4 + j] * scale;
            d_x16[(size_t)row*DD + idx[h] + j] = __float2half_rn(v);
        }
}

__global__ void transpose_half_kernel(const float* __restrict__ in,
                                      __half* __restrict__ outh,
                                      int R, int C) {
    __shared__ float t[32][33];
    size_t boff = (size_t)blockIdx.z * R * C;
    int c0 = blockIdx.x * 32, r0 = blockIdx.y * 32;
    int tx = threadIdx.x, ty = threadIdx.y;
    #pragma unroll
    for (int i = ty; i < 32; i += 8)
        t[i][tx] = in[boff + (size_t)(r0 + i) * C + c0 + tx];
    __syncthreads();
    #pragma unroll
    for (int i = ty; i < 32; i += 8) {
        size_t idx = boff + (size_t)(c0 + i) * R + r0 + tx;
        outh[idx] = __float2half_rn(t[tx][i]);
    }
}

// ============================================================
// Epilogues
// ============================================================
struct EpiU {
    int rowBase, colBase;
    const float* buv;
    __device__ void operator()(int r, int c, float v0, float v1) const {
        int row = rowBase + r;
        float s0 = v0 + buv[colBase + c];
        float s1 = v1 + buv[colBase + c + 1];
        s0 = s0 / (1.0f + __expf(-s0));
        s1 = s1 / (1.0f + __expf(-s1));
        *reinterpret_cast<__half2*>(d_u16 + (size_t)row*HH + colBase + c) =
            __halves2half2(__float2half_rn(s0), __float2half_rn(s1));
    }
};

#define VST 136
struct EpiVStage {
    __half* vsm;
    int colBase;
    const float* buv;
    __device__ void operator()(int r, int c, float v0, float v1) const {
        float s0 = v0 + buv[colBase + c];
        float s1 = v1 + buv[colBase + c + 1];
        s0 = s0 / (1.0f + __expf(-s0));
        s1 = s1 / (1.0f + __expf(-s1));
        vsm[(size_t)c * VST + r]       = __float2half_rn(s0);
        vsm[(size_t)(c + 1) * VST + r] = __float2half_rn(s1);
    }
};

struct EpiQKGen {
    int rowBase;
    const float *buv, *gamma, *beta;
    __device__ void operator()(int r, int c, float v0, float v1) const {
        int row = rowBase + r;
        float vv[2] = {v0, v1};
        #pragma unroll
        for (int i = 0; i < 2; i++) {
            int s = c + i;
            float val = vv[i] + buv[2*HH + s];
            val = val / (1.0f + __expf(-val));
            float vq = val * gamma[s]      + beta[s];
            float vk = val * gamma[SS + s] + beta[SS + s];
            size_t qi = (size_t)row*SS + s;
            d_q16[qi] = __float2half_rn(vq);
            d_k16[qi] = __float2half_rn(vk);
        }
    }
};

struct EpiO {
    int rowBase, colBase;
    const float* bo;
    float* out;
    __device__ void operator()(int r, int c, float v0, float v1) const {
        int row = rowBase + r;
        int col = colBase + c;
        float2 o = {v0 + bo[col], v1 + bo[col + 1]};
        *reinterpret_cast<float2*>(out + (size_t)row*DD + col) = o;
    }
};

// ============================================================
// GEMM kernels
// ============================================================
__global__ void __launch_bounds__(256, 2)
k_uv(const float* __restrict__ buv, const float* __restrict__ gamma,
     const float* __restrict__ beta) {
    extern __shared__ char smem[];
    int rowBase = blockIdx.y * 128, colBase = blockIdx.x * 128;
    const __half* A = d_x16 + (size_t)rowBase * DD;
    const __half* B = d_wuvT16 + (size_t)colBase * DD;

    if (colBase < HH) {
        EpiU epi{rowBase, colBase, buv};
        core_f16s<false>(A, DD, B, DD, DD, smem, epi);
    } else if (colBase < 2*HH) {
        __half* vsm = reinterpret_cast<__half*>(smem);
        EpiVStage epi{vsm, colBase, buv};
        core_f16s<true>(A, DD, B, DD, DD, smem, epi);
        __syncthreads();
        int b  = rowBase / NN;
        int m0 = rowBase % NN;
        int h0 = colBase - HH;
        int tid = threadIdx.x;
        int h = tid >> 1;
        int part = (tid & 1) * 64;
        const uint4* src = reinterpret_cast<const uint4*>(vsm + (size_t)h * VST + part);
        __half* dstp = d_vT + ((size_t)b*HH + h0 + h)*NN + m0 + part;
        uint4* dst = reinterpret_cast<uint4*>(dstp);
        #pragma unroll
        for (int j = 0; j < 8; j++) dst[j] = src[j];
    } else {
        EpiQKGen epi{rowBase, buv, gamma, beta};
        core_f16s<false>(A, DD, B, DD, DD, smem, epi);
    }
}

// ============================================================
// Fused attention: gated = u * (relu(q k^T / sqrt(S))^2 @ v)
// CTA: 128 rows x 128 h-cols; loops over 16 key-chunks of 128.
// Smem: Q 32K persistent + 3 x 64K (K 32K | V 32K) pipeline buffers = 224K.
// Each warp: 16 rows; P (16x128) lives in registers between the two MMAs.
// ============================================================
#define ATTN_SMEM (32768 + 3*65536)

__global__ void __launch_bounds__(256, 1)
k_attn() {
    extern __shared__ char smem[];
    uint32_t sb = smem_u32(smem);
    int tid = threadIdx.x, lane = tid & 31, warp = tid >> 5;
    int b = blockIdx.z, rowBase = blockIdx.y * 128, h0 = blockIdx.x * 128;
    size_t ra = (size_t)b * NN + rowBase;
    const __half* Q  = d_q16 + ra * SS;
    const __half* Kp = d_k16 + (size_t)b * NN * SS;
    const __half* Vp = d_vT  + ((size_t)b * HH + h0) * NN;

    // Q tile: two 128x64 sub-chunks at sb+0, sb+16K
    load_oper<128>(sb,         Q, SS, 0,  tid);
    load_oper<128>(sb + 16384, Q, SS, 64, tid);

    const int NC = NN / 128;   // 16 key chunks

    // chunk buffer layout: slot i at sb+32K+i*64K: K0 | K1 | V0 | V1 (16K each)
    // prologue: chunks 0, 1 (chunk 0 grouped with Q)
    {
        uint32_t st = sb + 32768;
        load_oper<128>(st,         Kp, SS, 0,  tid);
        load_oper<128>(st + 16384, Kp, SS, 64, tid);
        load_oper<128>(st + 32768, Vp, NN, 0,  tid);
        load_oper<128>(st + 49152, Vp, NN, 64, tid);
    }
    CP_COMMIT();
    {
        uint32_t st = sb + 32768 + 65536;
        const __half* Kc = Kp + (size_t)128 * SS;
        load_oper<128>(st,         Kc, SS, 0,  tid);
        load_oper<128>(st + 16384, Kc, SS, 64, tid);
        load_oper<128>(st + 32768, Vp, NN, 128, tid);
        load_oper<128>(st + 49152, Vp, NN, 192, tid);
    }
    CP_COMMIT();

    float acc2[16][4] = {};

    for (int mc = 0; mc < NC; mc++) {
        CP_WAIT1();          // chunk mc resident (mc+1 may be in flight)
        __syncthreads();     // all warps done with chunk mc-1's buffer
        if (mc + 2 < NC) {
            uint32_t st = sb + 32768 + ((mc + 2) % 3) * 65536;
            const __half* Kc = Kp + (size_t)((mc + 2) * 128) * SS;
            load_oper<128>(st,         Kc, SS, 0,  tid);
            load_oper<128>(st + 16384, Kc, SS, 64, tid);
            load_oper<128>(st + 32768, Vp, NN, (mc + 2) * 128,      tid);
            load_oper<128>(st + 49152, Vp, NN, (mc + 2) * 128 + 64, tid);
        }
        CP_COMMIT();

        uint32_t st = sb + 32768 + (mc % 3) * 65536;

        // ---- stage 1: P = q @ k^T (contraction over S=128) ----
        float P[16][4] = {};
        #pragma unroll
        for (int s = 0; s < 2; s++) {
            uint32_t qb = sb + s * 16384;
            uint32_t kb = st + s * 16384;
            #pragma unroll
            for (int ks = 0; ks < 4; ks++) {
                uint32_t a[4];
                {
                    int row = warp * 16 + (lane & 15);
                    int gi  = ks * 2 + (lane >> 4);
                    LDSM_X4(a[0], a[1], a[2], a[3],
                            qb + row * 128 + ((gi ^ (row & 7)) * 16));
                }
                uint32_t bf[16][2];
                #pragma unroll
                for (int np = 0; np < 8; np++) {
                    int row = np * 16 + (lane & 7) + ((lane >> 4) << 3);
                    int gi  = ks * 2 + ((lane >> 3) & 1);
                    LDSM_X4(bf[2*np][0], bf[2*np][1], bf[2*np+1][0], bf[2*np+1][1],
                            kb + row * 128 + ((gi ^ (row & 7)) * 16));
                }
                #pragma unroll
                for (int nt = 0; nt < 16; nt++)
                    MMA_F16(P[nt], a, bf[nt]);
            }
        }

        // ---- relu^2 * rsqrtS, convert acc fragments -> A fragments ----
        #pragma unroll
        for (int nt = 0; nt < 16; nt++)
            #pragma unroll
            for (int e = 0; e < 4; e++) {
                float r = fmaxf(P[nt][e] * RSQRT_S, 0.0f);
                P[nt][e] = r * r;
            }
        uint32_t Af[8][4];
        #pragma unroll
        for (int j = 0; j < 8; j++) {
            Af[j][0] = packh2(P[2*j][0],   P[2*j][1]);
            Af[j][1] = packh2(P[2*j][2],   P[2*j][3]);
            Af[j][2] = packh2(P[2*j+1][0], P[2*j+1][1]);
            Af[j][3] = packh2(P[2*j+1][2], P[2*j+1][3]);
        }

        // ---- stage 2: acc2 += P @ vT-chunk (contraction over m=128) ----
        #pragma unroll
        for (int ks2 = 0; ks2 < 8; ks2++) {
            uint32_t vb = st + 32768 + (ks2 >> 2) * 16384;
            int lk = ks2 & 3;
            uint32_t bf[16][2];
            #pragma unroll
            for (int np = 0; np < 8; np++) {
                int row = np * 16 + (lane & 7) + ((lane >> 4) << 3);
                int gi  = lk * 2 + ((lane >> 3) & 1);
                LDSM_X4(bf[2*np][0], bf[2*np][1], bf[2*np+1][0], bf[2*np+1][1],
                        vb + row * 128 + ((gi ^ (row & 7)) * 16));
            }
            #pragma unroll
            for (int nt = 0; nt < 16; nt++)
                MMA_F16(acc2[nt], Af[ks2], bf[nt]);
        }
    }

    // ---- epilogue: gated = u * acc2 ----
    int r0 = warp * 16 + (lane >> 2);
    #pragma unroll
    for (int nt = 0; nt < 16; nt++) {
        int col = h0 + nt * 8 + (lane & 3) * 2;
        #pragma unroll
        for (int half = 0; half < 2; half++) {
            size_t rg = ra + r0 + half * 8;
            size_t idx = rg * HH + col;
            __half2 uu = *reinterpret_cast<const __half2*>(d_u16 + idx);
            float2 uf = __half22float2(uu);
            float g0 = uf.x * acc2[nt][half * 2];
            float g1 = uf.y * acc2[nt][half * 2 + 1];
            *reinterpret_cast<__half2*>(d_ghi + idx) =
                __halves2half2(__float2half_rn(g0), __float2half_rn(g1));
        }
    }
}

__global__ void __launch_bounds__(256, 2)
k_o(const float* __restrict__ bo, float* __restrict__ out) {
    extern __shared__ char smem[];
    int rowBase = blockIdx.y * 128, colBase = blockIdx.x * 128;
    EpiO epi{rowBase, colBase, bo, out};
    core_f16s<false>(d_ghi + (size_t)rowBase * HH, HH,
                     d_woT + (size_t)colBase * HH, HH,
                     HH, smem, epi);
}

// ============================================================
extern "C" void kernel_launch(void* const* d_in, const int* in_sizes, int n_in,
                              void* d_out, int out_size) {
    (void)in_sizes; (void)n_in; (void)out_size;
    const float* x     = (const float*)d_in[0];
    const float* g     = (const float*)d_in[1];
    const float* Wuv   = (const float*)d_in[2];
    const float* buv   = (const float*)d_in[3];
    const float* gamma = (const float*)d_in[4];
    const float* beta  = (const float*)d_in[5];
    const float* Wo    = (const float*)d_in[6];
    const float* bo    = (const float*)d_in[7];
    float* out = (float*)d_out;

    static int smem_set = 0;
    if (!smem_set) {
        cudaFuncSetAttribute(k_uv,   cudaFuncAttributeMaxDynamicSharedMemorySize, SMEM_S1);
        cudaFuncSetAttribute(k_attn, cudaFuncAttributeMaxDynamicSharedMemorySize, ATTN_SMEM);
        cudaFuncSetAttribute(k_o,    cudaFuncAttributeMaxDynamicSharedMemorySize, SMEM_S1);
        smem_set = 1;
    }

    prep_x_kernel<<<BNROWS/8, dim3(32, 8)>>>(x, g);

    {   // W_uv: [D=256][E=1152] -> [E][D] fp16
        __half* th;
        cudaGetSymbolAddress((void**)&th, d_wuvT16);
        transpose_half_kernel<<<dim3(EE/32, DD/32, 1), dim3(32, 8)>>>(Wuv, th, DD, EE);
    }
    {   // W_o: [H=512][D=256] -> [D][H] fp16
        __half* th;
        cudaGetSymbolAddress((void**)&th, d_woT);
        transpose_half_kernel<<<dim3(DD/32, HH/32, 1), dim3(32, 8)>>>(Wo, th, HH, DD);
    }

    k_uv<<<dim3(EE/128, BNROWS/128), 256, SMEM_S1>>>(buv, gamma, beta);
    k_attn<<<dim3(HH/128, NN/128, BB), 256, ATTN_SMEM>>>();
    k_o<<<dim3(DD/128, BNROWS/128), 256, SMEM_S1>>>(bo, out);
}

// round 16
// speedup vs baseline: 1.4051x; 1.4051x over previous
#include <cuda_runtime.h>
#include <cuda_fp16.h>
#include <cstdint>
#include <math.h>

// Problem constants
#define BB 8
#define NN 2048
#define DD 256
#define SS 128
#define HH 512
#define EE 1152          // 2H + S
#define BNROWS (BB*NN)   // 16384
#define RSQRT_S 0.08838834764831845f  // 1/sqrt(128)

// ---- scratch (allocation-free rule: __device__ globals) ----
__device__ __half d_x16[(size_t)BNROWS*DD];          // xn fp16 (truncated)
__device__ __half d_u16[(size_t)BNROWS*HH];          // u fp16
__device__ __half d_q16[(size_t)BNROWS*SS];          // q fp16
__device__ __half d_k16[(size_t)BNROWS*SS];          // k fp16
__device__ __half d_vT[(size_t)BB*HH*NN];            // [b][h][m] fp16
__device__ __half d_ahi[(size_t)BB*NN*NN];           // attn [b][n][m] fp16
__device__ __half d_ghi[(size_t)BNROWS*HH];          // gated fp16
__device__ __half d_wuvT16[(size_t)EE*DD];           // W_uv^T [e][d] fp16
__device__ __half d_woT[(size_t)DD*HH];              // W_o^T [d][h] fp16

// ============================================================
// Helpers
// ============================================================
__device__ __forceinline__ uint32_t smem_u32(const void* p) {
    uint32_t a;
    asm("{ .reg .u64 t; cvta.to.shared.u64 t, %1; cvt.u32.u64 %0, t; }"
        : "=r"(a) : "l"(p));
    return a;
}

#define LDSM_X4(r0, r1, r2, r3, addr) \
    asm volatile("ldmatrix.sync.aligned.m8n8.x4.shared.b16 {%0,%1,%2,%3}, [%4];" \
        : "=r"(r0), "=r"(r1), "=r"(r2), "=r"(r3) : "r"(addr))

#define MMA_F16(d, a, b) \
    asm volatile("mma.sync.aligned.m16n8k16.row.col.f32.f16.f16.f32 " \
        "{%0,%1,%2,%3}, {%4,%5,%6,%7}, {%8,%9}, {%0,%1,%2,%3};" \
        : "+f"((d)[0]), "+f"((d)[1]), "+f"((d)[2]), "+f"((d)[3]) \
        : "r"((a)[0]), "r"((a)[1]), "r"((a)[2]), "r"((a)[3]), \
          "r"((b)[0]), "r"((b)[1]))

__device__ __forceinline__ void cp16(uint32_t dst, const void* src) {
    asm volatile("cp.async.cg.shared.global [%0], [%1], 16;"
        :: "r"(dst), "l"(src));
}
#define CP_COMMIT() asm volatile("cp.async.commit_group;" ::: "memory")
#define CP_WAIT1()  asm volatile("cp.async.wait_group 1;" ::: "memory")

__device__ __forceinline__ uint32_t packh2(float x, float y) {
    __half2 h = __floats2half2_rn(x, y);
    return *reinterpret_cast<uint32_t*>(&h);
}

// 16B granule loader: ROWS*8 granules strided by 256 threads, 128B rows,
// swizzle gi ^= row&7.
template <int ROWS, class T>
__device__ __forceinline__ void load_oper(uint32_t dstBase, const T* src,
                                          int ld, int kt, int tid) {
    #pragma unroll
    for (int j = 0; j < ROWS*8/256; j++) {
        int g = tid + j * 256;
        int row = g >> 3;
        int gi  = g & 7;
        int gis = gi ^ (row & 7);
        cp16(dstBase + row * 128 + gis * 16, src + (size_t)row * ld + kt + gi * 8);
    }
}

// ============================================================
// fp16 single-term core: BM=128, BN=128, BK=64, 3-stage, 2 CTAs/SM.
// Stage = Ah 16K | Bh 16K = 32KB, 3 stages (96KB). wait_group 1.
// ============================================================
#define STAGE_S  32768
#define SMEM_S1  (3*STAGE_S)

__device__ __forceinline__ void load_chunk_s(uint32_t sb, int stage,
        const __half* Ah, int ldA, const __half* Bh, int ldB, int kt, int tid) {
    uint32_t st = sb + stage * STAGE_S;
    load_oper<128>(st,         Ah, ldA, kt, tid);
    load_oper<128>(st + 16384, Bh, ldB, kt, tid);
}

__device__ __forceinline__ void compute_chunk_s(uint32_t st, int lane, int wm, int wn,
                                                float acc[2][8][4]) {
    const uint32_t aH = st, bH = st + 16384;
    #pragma unroll
    for (int ks = 0; ks < 4; ks++) {
        uint32_t Ahf[2][4];
        #pragma unroll
        for (int mi = 0; mi < 2; mi++) {
            int row = wm * 32 + mi * 16 + (lane & 15);
            int gi  = ks * 2 + (lane >> 4);
            uint32_t off = row * 128 + ((gi ^ (row & 7)) * 16);
            LDSM_X4(Ahf[mi][0], Ahf[mi][1], Ahf[mi][2], Ahf[mi][3], aH + off);
        }
        uint32_t Bhf[8][2];
        #pragma unroll
        for (int np = 0; np < 4; np++) {
            int row = wn * 64 + np * 16 + (lane & 7) + ((lane >> 4) << 3);
            int gi  = ks * 2 + ((lane >> 3) & 1);
            uint32_t off = row * 128 + ((gi ^ (row & 7)) * 16);
            LDSM_X4(Bhf[2*np][0], Bhf[2*np][1], Bhf[2*np+1][0], Bhf[2*np+1][1], bH + off);
        }
        #pragma unroll
        for (int mi = 0; mi < 2; mi++)
            #pragma unroll
            for (int ni = 0; ni < 8; ni++)
                MMA_F16(acc[mi][ni], Ahf[mi], Bhf[ni]);
    }
}

template <bool SYNC_BEFORE_EPI, class Epi>
__device__ __forceinline__ void core_f16s(
        const __half* Ah, int ldA, const __half* Bh, int ldB,
        int K, char* smem, Epi epi) {
    uint32_t sb = smem_u32(smem);
    int tid = threadIdx.x;
    int lane = tid & 31, warp = tid >> 5;
    int wm = warp & 3, wn = warp >> 2;

    float acc[2][8][4] = {};
    const int nc = K / 64;

    load_chunk_s(sb, 0, Ah, ldA, Bh, ldB, 0, tid);
    CP_COMMIT();
    if (nc > 1) load_chunk_s(sb, 1, Ah, ldA, Bh, ldB, 64, tid);
    CP_COMMIT();

    for (int c = 0; c < nc; c++) {
        CP_WAIT1();
        __syncthreads();
        if (c + 2 < nc) {
            int s = (c + 2) % 3;
            load_chunk_s(sb, s, Ah, ldA, Bh, ldB, (c + 2) * 64, tid);
        }
        CP_COMMIT();
        compute_chunk_s(sb + (c % 3) * STAGE_S, lane, wm, wn, acc);
    }

    if (SYNC_BEFORE_EPI) __syncthreads();

    #pragma unroll
    for (int mi = 0; mi < 2; mi++)
        #pragma unroll
        for (int ni = 0; ni < 8; ni++) {
            int r = wm * 32 + mi * 16 + (lane >> 2);
            int c = wn * 64 + ni * 8 + (lane & 3) * 2;
            epi(r,     c, acc[mi][ni][0], acc[mi][ni][1]);
            epi(r + 8, c, acc[mi][ni][2], acc[mi][ni][3]);
        }
}

// ============================================================
// prep: x -> normalized fp16 (truncated), vectorized stores
// ============================================================
__global__ void prep_x_kernel(const float* __restrict__ x,
                              const float* __restrict__ g) {
    int row  = blockIdx.x * blockDim.y + threadIdx.y;
    int lane = threadIdx.x;
    const float4* xr = reinterpret_cast<const float4*>(x + (size_t)row * DD);
    float4 a = xr[lane];
    float4 b = xr[lane + 32];
    float s = a.x*a.x + a.y*a.y + a.z*a.z + a.w*a.w
            + b.x*b.x + b.y*b.y + b.z*b.z + b.w*b.w;
    #pragma unroll
    for (int off = 16; off; off >>= 1) s += __shfl_xor_sync(0xffffffffu, s, off);
    s = __shfl_sync(0xffffffffu, s, 0);
    float norm = sqrtf(s * (1.0f / DD));
    float scale = g[0] / fmaxf(norm, 1e-5f);

    uint2 p0 = { packh2(a.x*scale, a.y*scale), packh2(a.z*scale, a.w*scale) };
    uint2 p1 = { packh2(b.x*scale, b.y*scale), packh2(b.z*scale, b.w*scale) };
    *reinterpret_cast<uint2*>(d_x16 + (size_t)row*DD + lane*4)       = p0;
    *reinterpret_cast<uint2*>(d_x16 + (size_t)row*DD + 128 + lane*4) = p1;
}

// transpose + fp16 truncate (W_uv, W_o)
__global__ void transpose_half_kernel(const float* __restrict__ in,
                                      __half* __restrict__ outh,
                                      int R, int C) {
    __shared__ float t[32][33];
    size_t boff = (size_t)blockIdx.z * R * C;
    int c0 = blockIdx.x * 32, r0 = blockIdx.y * 32;
    int tx = threadIdx.x, ty = threadIdx.y;
    #pragma unroll
    for (int i = ty; i < 32; i += 8)
        t[i][tx] = in[boff + (size_t)(r0 + i) * C + c0 + tx];
    __syncthreads();
    #pragma unroll
    for (int i = ty; i < 32; i += 8) {
        size_t idx = boff + (size_t)(c0 + i) * R + r0 + tx;
        outh[idx] = __float2half_rn(t[tx][i]);
    }
}

// ============================================================
// Epilogues
// ============================================================
struct EpiU {
    int rowBase, colBase;
    const float* buv;
    __device__ void operator()(int r, int c, float v0, float v1) const {
        int row = rowBase + r;
        float s0 = v0 + buv[colBase + c];
        float s1 = v1 + buv[colBase + c + 1];
        s0 = s0 / (1.0f + __expf(-s0));
        s1 = s1 / (1.0f + __expf(-s1));
        *reinterpret_cast<__half2*>(d_u16 + (size_t)row*HH + colBase + c) =
            __floats2half2_rn(s0, s1);
    }
};

// v tile: stage into smem [h][m] with padded stride 136 (16B-aligned rows)
#define VST 136
struct EpiVStage {
    __half* vsm;
    int colBase;
    const float* buv;
    __device__ void operator()(int r, int c, float v0, float v1) const {
        float s0 = v0 + buv[colBase + c];
        float s1 = v1 + buv[colBase + c + 1];
        s0 = s0 / (1.0f + __expf(-s0));
        s1 = s1 / (1.0f + __expf(-s1));
        vsm[(size_t)c * VST + r]       = __float2half_rn(s0);
        vsm[(size_t)(c + 1) * VST + r] = __float2half_rn(s1);
    }
};

struct EpiQKGen {
    int rowBase;
    const float *buv, *gamma, *beta;
    __device__ void operator()(int r, int c, float v0, float v1) const {
        int row = rowBase + r;
        int s = c;   // even, pairs contiguous
        float val0 = v0 + buv[2*HH + s];
        float val1 = v1 + buv[2*HH + s + 1];
        val0 = val0 / (1.0f + __expf(-val0));
        val1 = val1 / (1.0f + __expf(-val1));
        float q0 = val0 * gamma[s]     + beta[s];
        float q1 = val1 * gamma[s + 1] + beta[s + 1];
        float k0 = val0 * gamma[SS + s]     + beta[SS + s];
        float k1 = val1 * gamma[SS + s + 1] + beta[SS + s + 1];
        size_t qi = (size_t)row*SS + s;
        *reinterpret_cast<__half2*>(d_q16 + qi) = __floats2half2_rn(q0, q1);
        *reinterpret_cast<__half2*>(d_k16 + qi) = __floats2half2_rn(k0, k1);
    }
};

struct EpiQK {
    size_t rowOff;
    int colBase;
    __device__ void operator()(int r, int c, float v0, float v1) const {
        size_t idx = (rowOff + r) * NN + colBase + c;
        float a0 = fmaxf(v0 * RSQRT_S, 0.0f); a0 *= a0;
        float a1 = fmaxf(v1 * RSQRT_S, 0.0f); a1 *= a1;
        *reinterpret_cast<__half2*>(d_ahi + idx) = __floats2half2_rn(a0, a1);
    }
};

struct EpiAV {
    size_t rowOff;
    int colBase;
    __device__ void operator()(int r, int c, float v0, float v1) const {
        size_t rg = rowOff + r;
        size_t idx = rg * HH + colBase + c;
        __half2 uu = *reinterpret_cast<const __half2*>(d_u16 + idx);
        float2 uf = __half22float2(uu);
        *reinterpret_cast<__half2*>(d_ghi + idx) =
            __floats2half2_rn(uf.x * v0, uf.y * v1);
    }
};

struct EpiO {
    int rowBase, colBase;
    const float* bo;
    float* out;
    __device__ void operator()(int r, int c, float v0, float v1) const {
        int row = rowBase + r;
        int col = colBase + c;
        float2 o = {v0 + bo[col], v1 + bo[col + 1]};
        *reinterpret_cast<float2*>(out + (size_t)row*DD + col) = o;
    }
};

// ============================================================
// GEMM kernels
// ============================================================
// full UV GEMM: grid (E/128=9, BNROWS/128); col range selects epilogue
__global__ void __launch_bounds__(256, 2)
k_uv(const float* __restrict__ buv, const float* __restrict__ gamma,
     const float* __restrict__ beta) {
    extern __shared__ char smem[];
    int rowBase = blockIdx.y * 128, colBase = blockIdx.x * 128;
    const __half* A = d_x16 + (size_t)rowBase * DD;
    const __half* B = d_wuvT16 + (size_t)colBase * DD;

    if (colBase < HH) {
        EpiU epi{rowBase, colBase, buv};
        core_f16s<false>(A, DD, B, DD, DD, smem, epi);
    } else if (colBase < 2*HH) {
        __half* vsm = reinterpret_cast<__half*>(smem);
        EpiVStage epi{vsm, colBase, buv};
        core_f16s<true>(A, DD, B, DD, DD, smem, epi);
        __syncthreads();
        // coalesced writeout: vT[b][h0+h][m0 .. m0+127]
        int b  = rowBase / NN;
        int m0 = rowBase % NN;
        int h0 = colBase - HH;
        int tid = threadIdx.x;
        int h = tid >> 1;
        int part = (tid & 1) * 64;
        const uint4* src = reinterpret_cast<const uint4*>(vsm + (size_t)h * VST + part);
        __half* dstp = d_vT + ((size_t)b*HH + h0 + h)*NN + m0 + part;
        uint4* dst = reinterpret_cast<uint4*>(dstp);
        #pragma unroll
        for (int j = 0; j < 8; j++) dst[j] = src[j];
    } else {
        EpiQKGen epi{rowBase, buv, gamma, beta};
        core_f16s<false>(A, DD, B, DD, DD, smem, epi);
    }
}

__global__ void __launch_bounds__(256, 2)
k_qk() {
    extern __shared__ char smem[];
    int b = blockIdx.z, rowBase = blockIdx.y * 128, colBase = blockIdx.x * 128;
    size_t ra = (size_t)b * NN + rowBase;
    size_t rb = (size_t)b * NN + colBase;
    EpiQK epi{ra, colBase};
    core_f16s<false>(d_q16 + ra * SS, SS,
                     d_k16 + rb * SS, SS,
                     SS, smem, epi);
}

__global__ void __launch_bounds__(256, 2)
k_av() {
    extern __shared__ char smem[];
    int b = blockIdx.z, rowBase = blockIdx.y * 128, colBase = blockIdx.x * 128;
    size_t ra = (size_t)b * NN + rowBase;
    size_t hb = (size_t)b * HH + colBase;
    EpiAV epi{ra, colBase};
    core_f16s<false>(d_ahi + ra * NN, NN,
                     d_vT + hb * NN, NN,
                     NN, smem, epi);
}

__global__ void __launch_bounds__(256, 2)
k_o(const float* __restrict__ bo, float* __restrict__ out) {
    extern __shared__ char smem[];
    int rowBase = blockIdx.y * 128, colBase = blockIdx.x * 128;
    EpiO epi{rowBase, colBase, bo, out};
    core_f16s<false>(d_ghi + (size_t)rowBase * HH, HH,
                     d_woT + (size_t)colBase * HH, HH,
                     HH, smem, epi);
}

// ============================================================
extern "C" void kernel_launch(void* const* d_in, const int* in_sizes, int n_in,
                              void* d_out, int out_size) {
    (void)in_sizes; (void)n_in; (void)out_size;
    const float* x     = (const float*)d_in[0];
    const float* g     = (const float*)d_in[1];
    const float* Wuv   = (const float*)d_in[2];
    const float* buv   = (const float*)d_in[3];
    const float* gamma = (const float*)d_in[4];
    const float* beta  = (const float*)d_in[5];
    const float* Wo    = (const float*)d_in[6];
    const float* bo    = (const float*)d_in[7];
    float* out = (float*)d_out;

    static int smem_set = 0;
    if (!smem_set) {
        cudaFuncSetAttribute(k_uv, cudaFuncAttributeMaxDynamicSharedMemorySize, SMEM_S1);
        cudaFuncSetAttribute(k_qk, cudaFuncAttributeMaxDynamicSharedMemorySize, SMEM_S1);
        cudaFuncSetAttribute(k_av, cudaFuncAttributeMaxDynamicSharedMemorySize, SMEM_S1);
        cudaFuncSetAttribute(k_o,  cudaFuncAttributeMaxDynamicSharedMemorySize, SMEM_S1);
        smem_set = 1;
    }

    prep_x_kernel<<<BNROWS/8, dim3(32, 8)>>>(x, g);

    {   // W_uv: [D=256][E=1152] -> [E][D] fp16
        __half* th;
        cudaGetSymbolAddress((void**)&th, d_wuvT16);
        transpose_half_kernel<<<dim3(EE/32, DD/32, 1), dim3(32, 8)>>>(Wuv, th, DD, EE);
    }
    {   // W_o: [H=512][D=256] -> [D][H] fp16
        __half* th;
        cudaGetSymbolAddress((void**)&th, d_woT);
        transpose_half_kernel<<<dim3(DD/32, HH/32, 1), dim3(32, 8)>>>(Wo, th, HH, DD);
    }

    k_uv<<<dim3(EE/128, BNROWS/128), 256, SMEM_S1>>>(buv, gamma, beta);
    k_qk<<<dim3(NN/128, NN/128, BB), 256, SMEM_S1>>>();
    k_av<<<dim3(HH/128, NN/128, BB), 256, SMEM_S1>>>();
    k_o<<<dim3(DD/128, BNROWS/128), 256, SMEM_S1>>>(bo, out);
}

// round 17
// speedup vs baseline: 1.4199x; 1.0105x over previous
#include <cuda_runtime.h>
#include <cuda_fp16.h>
#include <cstdint>
#include <math.h>

// Problem constants
#define BB 8
#define NN 2048
#define DD 256
#define SS 128
#define HH 512
#define EE 1152          // 2H + S
#define BNROWS (BB*NN)   // 16384
#define RSQRT_S 0.08838834764831845f  // 1/sqrt(128)

// ---- scratch (allocation-free rule: __device__ globals) ----
__device__ __half d_x16[(size_t)BNROWS*DD];          // xn fp16 (truncated)
__device__ __half d_u16[(size_t)BNROWS*HH];          // u fp16
__device__ __half d_q16[(size_t)BNROWS*SS];          // q fp16
__device__ __half d_k16[(size_t)BNROWS*SS];          // k fp16
__device__ __half d_vT[(size_t)BB*HH*NN];            // [b][h][m] fp16
__device__ __half d_ahi[(size_t)BB*NN*NN];           // attn [b][n][m] fp16
__device__ __half d_ghi[(size_t)BNROWS*HH];          // gated fp16
__device__ __half d_wuvT16[(size_t)EE*DD];           // W_uv^T [e][d] fp16
__device__ __half d_woT[(size_t)DD*HH];              // W_o^T [d][h] fp16

// ============================================================
// Helpers
// ============================================================
__device__ __forceinline__ uint32_t smem_u32(const void* p) {
    uint32_t a;
    asm("{ .reg .u64 t; cvta.to.shared.u64 t, %1; cvt.u32.u64 %0, t; }"
        : "=r"(a) : "l"(p));
    return a;
}

#define LDSM_X4(r0, r1, r2, r3, addr) \
    asm volatile("ldmatrix.sync.aligned.m8n8.x4.shared.b16 {%0,%1,%2,%3}, [%4];" \
        : "=r"(r0), "=r"(r1), "=r"(r2), "=r"(r3) : "r"(addr))

#define MMA_F16(d, a, b) \
    asm volatile("mma.sync.aligned.m16n8k16.row.col.f32.f16.f16.f32 " \
        "{%0,%1,%2,%3}, {%4,%5,%6,%7}, {%8,%9}, {%0,%1,%2,%3};" \
        : "+f"((d)[0]), "+f"((d)[1]), "+f"((d)[2]), "+f"((d)[3]) \
        : "r"((a)[0]), "r"((a)[1]), "r"((a)[2]), "r"((a)[3]), \
          "r"((b)[0]), "r"((b)[1]))

__device__ __forceinline__ void cp16(uint32_t dst, const void* src) {
    asm volatile("cp.async.cg.shared.global [%0], [%1], 16;"
        :: "r"(dst), "l"(src));
}
#define CP_COMMIT() asm volatile("cp.async.commit_group;" ::: "memory")
#define CP_WAIT1()  asm volatile("cp.async.wait_group 1;" ::: "memory")

__device__ __forceinline__ uint32_t packh2(float x, float y) {
    __half2 h = __floats2half2_rn(x, y);
    return *reinterpret_cast<uint32_t*>(&h);
}

// 16B granule loader: ROWS*8 granules strided by 256 threads, 128B rows,
// swizzle gi ^= row&7.
template <int ROWS, class T>
__device__ __forceinline__ void load_oper(uint32_t dstBase, const T* src,
                                          int ld, int kt, int tid) {
    #pragma unroll
    for (int j = 0; j < ROWS*8/256; j++) {
        int g = tid + j * 256;
        int row = g >> 3;
        int gi  = g & 7;
        int gis = gi ^ (row & 7);
        cp16(dstBase + row * 128 + gis * 16, src + (size_t)row * ld + kt + gi * 8);
    }
}

// ============================================================
// fp16 single-term core: BM=128, BN=128, BK=64, 3-stage, 2 CTAs/SM.
// Stage = Ah 16K | Bh 16K = 32KB, 3 stages (96KB). wait_group 1.
// ============================================================
#define STAGE_S  32768
#define SMEM_S1  (3*STAGE_S)

__device__ __forceinline__ void load_chunk_s(uint32_t sb, int stage,
        const __half* Ah, int ldA, const __half* Bh, int ldB, int kt, int tid) {
    uint32_t st = sb + stage * STAGE_S;
    load_oper<128>(st,         Ah, ldA, kt, tid);
    load_oper<128>(st + 16384, Bh, ldB, kt, tid);
}

__device__ __forceinline__ void compute_chunk_s(uint32_t st, int lane, int wm, int wn,
                                                float acc[2][8][4]) {
    const uint32_t aH = st, bH = st + 16384;
    #pragma unroll
    for (int ks = 0; ks < 4; ks++) {
        uint32_t Ahf[2][4];
        #pragma unroll
        for (int mi = 0; mi < 2; mi++) {
            int row = wm * 32 + mi * 16 + (lane & 15);
            int gi  = ks * 2 + (lane >> 4);
            uint32_t off = row * 128 + ((gi ^ (row & 7)) * 16);
            LDSM_X4(Ahf[mi][0], Ahf[mi][1], Ahf[mi][2], Ahf[mi][3], aH + off);
        }
        uint32_t Bhf[8][2];
        #pragma unroll
        for (int np = 0; np < 4; np++) {
            int row = wn * 64 + np * 16 + (lane & 7) + ((lane >> 4) << 3);
            int gi  = ks * 2 + ((lane >> 3) & 1);
            uint32_t off = row * 128 + ((gi ^ (row & 7)) * 16);
            LDSM_X4(Bhf[2*np][0], Bhf[2*np][1], Bhf[2*np+1][0], Bhf[2*np+1][1], bH + off);
        }
        #pragma unroll
        for (int mi = 0; mi < 2; mi++)
            #pragma unroll
            for (int ni = 0; ni < 8; ni++)
                MMA_F16(acc[mi][ni], Ahf[mi], Bhf[ni]);
    }
}

template <bool SYNC_BEFORE_EPI, class Epi>
__device__ __forceinline__ void core_f16s(
        const __half* Ah, int ldA, const __half* Bh, int ldB,
        int K, char* smem, Epi epi) {
    uint32_t sb = smem_u32(smem);
    int tid = threadIdx.x;
    int lane = tid & 31, warp = tid >> 5;
    int wm = warp & 3, wn = warp >> 2;

    float acc[2][8][4] = {};
    const int nc = K / 64;

    load_chunk_s(sb, 0, Ah, ldA, Bh, ldB, 0, tid);
    CP_COMMIT();
    if (nc > 1) load_chunk_s(sb, 1, Ah, ldA, Bh, ldB, 64, tid);
    CP_COMMIT();

    for (int c = 0; c < nc; c++) {
        CP_WAIT1();
        __syncthreads();
        if (c + 2 < nc) {
            int s = (c + 2) % 3;
            load_chunk_s(sb, s, Ah, ldA, Bh, ldB, (c + 2) * 64, tid);
        }
        CP_COMMIT();
        compute_chunk_s(sb + (c % 3) * STAGE_S, lane, wm, wn, acc);
    }

    if (SYNC_BEFORE_EPI) __syncthreads();

    #pragma unroll
    for (int mi = 0; mi < 2; mi++)
        #pragma unroll
        for (int ni = 0; ni < 8; ni++) {
            int r = wm * 32 + mi * 16 + (lane >> 2);
            int c = wn * 64 + ni * 8 + (lane & 3) * 2;
            epi(r,     c, acc[mi][ni][0], acc[mi][ni][1]);
            epi(r + 8, c, acc[mi][ni][2], acc[mi][ni][3]);
        }
}

// ============================================================
// prep: x -> normalized fp16 (truncated), vectorized stores
// ============================================================
__global__ void prep_x_kernel(const float* __restrict__ x,
                              const float* __restrict__ g) {
    int row  = blockIdx.x * blockDim.y + threadIdx.y;
    int lane = threadIdx.x;
    const float4* xr = reinterpret_cast<const float4*>(x + (size_t)row * DD);
    float4 a = xr[lane];
    float4 b = xr[lane + 32];
    float s = a.x*a.x + a.y*a.y + a.z*a.z + a.w*a.w
            + b.x*b.x + b.y*b.y + b.z*b.z + b.w*b.w;
    #pragma unroll
    for (int off = 16; off; off >>= 1) s += __shfl_xor_sync(0xffffffffu, s, off);
    s = __shfl_sync(0xffffffffu, s, 0);
    float norm = sqrtf(s * (1.0f / DD));
    float scale = g[0] / fmaxf(norm, 1e-5f);

    uint2 p0 = { packh2(a.x*scale, a.y*scale), packh2(a.z*scale, a.w*scale) };
    uint2 p1 = { packh2(b.x*scale, b.y*scale), packh2(b.z*scale, b.w*scale) };
    *reinterpret_cast<uint2*>(d_x16 + (size_t)row*DD + lane*4)       = p0;
    *reinterpret_cast<uint2*>(d_x16 + (size_t)row*DD + 128 + lane*4) = p1;
}

// transpose + fp16 truncate (W_uv, W_o)
__global__ void transpose_half_kernel(const float* __restrict__ in,
                                      __half* __restrict__ outh,
                                      int R, int C) {
    __shared__ float t[32][33];
    size_t boff = (size_t)blockIdx.z * R * C;
    int c0 = blockIdx.x * 32, r0 = blockIdx.y * 32;
    int tx = threadIdx.x, ty = threadIdx.y;
    #pragma unroll
    for (int i = ty; i < 32; i += 8)
        t[i][tx] = in[boff + (size_t)(r0 + i) * C + c0 + tx];
    __syncthreads();
    #pragma unroll
    for (int i = ty; i < 32; i += 8) {
        size_t idx = boff + (size_t)(c0 + i) * R + r0 + tx;
        outh[idx] = __float2half_rn(t[tx][i]);
    }
}

// ============================================================
// Epilogues
// ============================================================
struct EpiU {
    int rowBase, colBase;
    const float* buv;
    __device__ void operator()(int r, int c, float v0, float v1) const {
        int row = rowBase + r;
        float s0 = v0 + buv[colBase + c];
        float s1 = v1 + buv[colBase + c + 1];
        s0 = s0 / (1.0f + __expf(-s0));
        s1 = s1 / (1.0f + __expf(-s1));
        *reinterpret_cast<__half2*>(d_u16 + (size_t)row*HH + colBase + c) =
            __floats2half2_rn(s0, s1);
    }
};

// v tile: stage into smem [h][m] with padded stride 136 (16B-aligned rows)
#define VST 136
struct EpiVStage {
    __half* vsm;
    int colBase;
    const float* buv;
    __device__ void operator()(int r, int c, float v0, float v1) const {
        float s0 = v0 + buv[colBase + c];
        float s1 = v1 + buv[colBase + c + 1];
        s0 = s0 / (1.0f + __expf(-s0));
        s1 = s1 / (1.0f + __expf(-s1));
        vsm[(size_t)c * VST + r]       = __float2half_rn(s0);
        vsm[(size_t)(c + 1) * VST + r] = __float2half_rn(s1);
    }
};

struct EpiQKGen {
    int rowBase;
    const float *buv, *gamma, *beta;
    __device__ void operator()(int r, int c, float v0, float v1) const {
        int row = rowBase + r;
        int s = c;   // even, pairs contiguous
        float val0 = v0 + buv[2*HH + s];
        float val1 = v1 + buv[2*HH + s + 1];
        val0 = val0 / (1.0f + __expf(-val0));
        val1 = val1 / (1.0f + __expf(-val1));
        float q0 = val0 * gamma[s]     + beta[s];
        float q1 = val1 * gamma[s + 1] + beta[s + 1];
        float k0 = val0 * gamma[SS + s]     + beta[SS + s];
        float k1 = val1 * gamma[SS + s + 1] + beta[SS + s + 1];
        size_t qi = (size_t)row*SS + s;
        *reinterpret_cast<__half2*>(d_q16 + qi) = __floats2half2_rn(q0, q1);
        *reinterpret_cast<__half2*>(d_k16 + qi) = __floats2half2_rn(k0, k1);
    }
};

struct EpiQK {
    size_t rowOff;
    int colBase;
    __device__ void operator()(int r, int c, float v0, float v1) const {
        size_t idx = (rowOff + r) * NN + colBase + c;
        float a0 = fmaxf(v0 * RSQRT_S, 0.0f); a0 *= a0;
        float a1 = fmaxf(v1 * RSQRT_S, 0.0f); a1 *= a1;
        *reinterpret_cast<__half2*>(d_ahi + idx) = __floats2half2_rn(a0, a1);
    }
};

struct EpiAV {
    size_t rowOff;
    int colBase;
    __device__ void operator()(int r, int c, float v0, float v1) const {
        size_t rg = rowOff + r;
        size_t idx = rg * HH + colBase + c;
        __half2 uu = *reinterpret_cast<const __half2*>(d_u16 + idx);
        float2 uf = __half22float2(uu);
        *reinterpret_cast<__half2*>(d_ghi + idx) =
            __floats2half2_rn(uf.x * v0, uf.y * v1);
    }
};

struct EpiO {
    int rowBase, colBase;
    const float* bo;
    float* out;
    __device__ void operator()(int r, int c, float v0, float v1) const {
        int row = rowBase + r;
        int col = colBase + c;
        float2 o = {v0 + bo[col], v1 + bo[col + 1]};
        *reinterpret_cast<float2*>(out + (size_t)row*DD + col) = o;
    }
};

// ============================================================
// GEMM kernels
// ============================================================
// full UV GEMM: grid (E/128=9, BNROWS/128); col range selects epilogue
__global__ void __launch_bounds__(256, 2)
k_uv(const float* __restrict__ buv, const float* __restrict__ gamma,
     const float* __restrict__ beta) {
    extern __shared__ char smem[];
    int rowBase = blockIdx.y * 128, colBase = blockIdx.x * 128;
    const __half* A = d_x16 + (size_t)rowBase * DD;
    const __half* B = d_wuvT16 + (size_t)colBase * DD;

    if (colBase < HH) {
        EpiU epi{rowBase, colBase, buv};
        core_f16s<false>(A, DD, B, DD, DD, smem, epi);
    } else if (colBase < 2*HH) {
        __half* vsm = reinterpret_cast<__half*>(smem);
        EpiVStage epi{vsm, colBase, buv};
        core_f16s<true>(A, DD, B, DD, DD, smem, epi);
        __syncthreads();
        // coalesced writeout: vT[b][h0+h][m0 .. m0+127]
        int b  = rowBase / NN;
        int m0 = rowBase % NN;
        int h0 = colBase - HH;
        int tid = threadIdx.x;
        int h = tid >> 1;
        int part = (tid & 1) * 64;
        const uint4* src = reinterpret_cast<const uint4*>(vsm + (size_t)h * VST + part);
        __half* dstp = d_vT + ((size_t)b*HH + h0 + h)*NN + m0 + part;
        uint4* dst = reinterpret_cast<uint4*>(dstp);
        #pragma unroll
        for (int j = 0; j < 8; j++) dst[j] = src[j];
    } else {
        EpiQKGen epi{rowBase, buv, gamma, beta};
        core_f16s<false>(A, DD, B, DD, DD, smem, epi);
    }
}

__global__ void __launch_bounds__(256, 2)
k_qk() {
    extern __shared__ char smem[];
    int b = blockIdx.z, rowBase = blockIdx.y * 128, colBase = blockIdx.x * 128;
    size_t ra = (size_t)b * NN + rowBase;
    size_t rb = (size_t)b * NN + colBase;
    EpiQK epi{ra, colBase};
    core_f16s<false>(d_q16 + ra * SS, SS,
                     d_k16 + rb * SS, SS,
                     SS, smem, epi);
}

// persistent k_av: exactly fills the 296 co-resident CTA slots; each CTA
// loops over tiles, eliminating wave-quantization idle (512 tiles / 296
// slots = 1.73 waves would otherwise round up to 2).
#define AV_TILES ((HH/128)*(NN/128)*BB)   // 512
__global__ void __launch_bounds__(256, 2)
k_av_persist() {
    extern __shared__ char smem[];
    for (int t = blockIdx.x; t < AV_TILES; t += gridDim.x) {
        int hB = t % (HH/128);
        int rB = (t / (HH/128)) % (NN/128);
        int b  = t / ((HH/128) * (NN/128));
        size_t ra = (size_t)b * NN + rB * 128;
        size_t hb = (size_t)b * HH + hB * 128;
        EpiAV epi{ra, hB * 128};
        core_f16s<false>(d_ahi + ra * NN, NN,
                         d_vT + hb * NN, NN,
                         NN, smem, epi);
        __syncthreads();   // epilogue/compute done before next tile's loads
    }
}

__global__ void __launch_bounds__(256, 2)
k_o(const float* __restrict__ bo, float* __restrict__ out) {
    extern __shared__ char smem[];
    int rowBase = blockIdx.y * 128, colBase = blockIdx.x * 128;
    EpiO epi{rowBase, colBase, bo, out};
    core_f16s<false>(d_ghi + (size_t)rowBase * HH, HH,
                     d_woT + (size_t)colBase * HH, HH,
                     HH, smem, epi);
}

// ============================================================
extern "C" void kernel_launch(void* const* d_in, const int* in_sizes, int n_in,
                              void* d_out, int out_size) {
    (void)in_sizes; (void)n_in; (void)out_size;
    const float* x     = (const float*)d_in[0];
    const float* g     = (const float*)d_in[1];
    const float* Wuv   = (const float*)d_in[2];
    const float* buv   = (const float*)d_in[3];
    const float* gamma = (const float*)d_in[4];
    const float* beta  = (const float*)d_in[5];
    const float* Wo    = (const float*)d_in[6];
    const float* bo    = (const float*)d_in[7];
    float* out = (float*)d_out;

    static int smem_set = 0;
    if (!smem_set) {
        cudaFuncSetAttribute(k_uv, cudaFuncAttributeMaxDynamicSharedMemorySize, SMEM_S1);
        cudaFuncSetAttribute(k_qk, cudaFuncAttributeMaxDynamicSharedMemorySize, SMEM_S1);
        cudaFuncSetAttribute(k_av_persist, cudaFuncAttributeMaxDynamicSharedMemorySize, SMEM_S1);
        cudaFuncSetAttribute(k_o,  cudaFuncAttributeMaxDynamicSharedMemorySize, SMEM_S1);
        smem_set = 1;
    }

    prep_x_kernel<<<BNROWS/8, dim3(32, 8)>>>(x, g);

    {   // W_uv: [D=256][E=1152] -> [E][D] fp16
        __half* th;
        cudaGetSymbolAddress((void**)&th, d_wuvT16);
        transpose_half_kernel<<<dim3(EE/32, DD/32, 1), dim3(32, 8)>>>(Wuv, th, DD, EE);
    }
    {   // W_o: [H=512][D=256] -> [D][H] fp16
        __half* th;
        cudaGetSymbolAddress((void**)&th, d_woT);
        transpose_half_kernel<<<dim3(DD/32, HH/32, 1), dim3(32, 8)>>>(Wo, th, HH, DD);
    }

    k_uv<<<dim3(EE/128, BNROWS/128), 256, SMEM_S1>>>(buv, gamma, beta);
    k_qk<<<dim3(NN/128, NN/128, BB), 256, SMEM_S1>>>();
    k_av_persist<<<296, 256, SMEM_S1>>>();
    k_o<<<dim3(DD/128, BNROWS/128), 256, SMEM_S1>>>(bo, out);
}